// round 14
// baseline (speedup 1.0000x reference)
#include <cuda_runtime.h>
#include <math.h>

#define B_   16
#define C_   1024
#define BC_  (B_ * C_)
#define EPSf  1e-12f
#define TINYf 1e-9f
#define ROWS_ 8

#define BCC_    ((size_t)BC_ * (size_t)C_)
#define OFF_SL  ((size_t)0)
#define OFF_SU  ((size_t)BC_)
#define OFF_LC  ((size_t)(2 * BC_))
#define OFF_UC  ((size_t)(2 * BC_) + BCC_)
#define OFF_LB  ((size_t)(2 * BC_) + 2 * BCC_)
#define OFF_UB  ((size_t)(2 * BC_) + 2 * BCC_ + BC_)

__device__ __forceinline__ float sqrt_apx(float x) {
    float r;
    asm("sqrt.approx.f32 %0, %1;" : "=f"(r) : "f"(x));
    return r;
}

// Single fused kernel: one block per 8 rows of one batch.
// __launch_bounds__(256, 7): 7 CTAs/SM -> concurrency 1036; grid 2048 runs
// as 2 nearly-full waves instead of 3 (one 31%-occupied tail wave).
__global__ __launch_bounds__(256, 7) void bs_kernel(
    const float* __restrict__ lower,
    const float* __restrict__ upper,
    float* __restrict__ out)
{
    const int row0 = blockIdx.x << 3;        // b*C + i0
    const int b    = row0 >> 10;
    const int i0   = row0 & (C_ - 1);
    const int tid  = threadIdx.x;
    const int j0   = tid << 2;

    const float* __restrict__ lrow = lower + (size_t)b * C_;
    const float* __restrict__ urow = upper + (size_t)b * C_;

    // j-chunk loads
    float4 lj = *reinterpret_cast<const float4*>(lrow + j0);
    float4 uj = *reinterpret_cast<const float4*>(urow + j0);
    const float* ljp = reinterpret_cast<const float*>(&lj);
    const float* ujp = reinterpret_cast<const float*>(&uj);

    // per-j exponentials (computed, not loaded)
    float Elj[4], Euj[4], Emj[4], wj[4];
    float pEl = 0.f, pEu = 0.f, pEm = 0.f, pEmM = 0.f;
#pragma unroll
    for (int k = 0; k < 4; ++k) {
        float l = ljp[k], u = ujp[k];
        Elj[k] = __expf(l);
        Euj[k] = __expf(u);
        Emj[k] = sqrt_apx(Elj[k] * Euj[k]);   // exp((l+u)/2)
        wj[k]  = u - l;
        pEl  += Elj[k];
        pEu  += Euj[k];
        pEm  += Emj[k];
        pEmM  = fmaf(Emj[k], 0.5f * (l + u), pEmM);
    }

    __shared__ float sred[16][256];
    __shared__ float sres[16];
    __shared__ float rowc[ROWS_][10];

    // block-reduce the 4 batch sums (warp w reduces var w)
    sred[0][tid] = pEl;
    sred[1][tid] = pEu;
    sred[2][tid] = pEm;
    sred[3][tid] = pEmM;
    __syncthreads();
    {
        const int warp = tid >> 5;
        const int lane = tid & 31;
        if (warp < 4) {
            float s = 0.f;
#pragma unroll
            for (int jj = 0; jj < 8; ++jj) s += sred[warp][lane + 32 * jj];
#pragma unroll
            for (int m = 16; m > 0; m >>= 1) s += __shfl_xor_sync(0xffffffffu, s, m);
            if (lane == 0) sres[warp] = s;
        }
    }
    __syncthreads();

    // per-row constants (8 threads)
    if (tid < ROWS_) {
        const int r   = tid;
        const int row = row0 + r;
        const float l_i  = lrow[i0 + r];
        const float u_i  = urow[i0 + r];
        const float El_i = __expf(l_i);
        const float Eu_i = __expf(u_i);
        const float ElNi = __expf(-l_i);
        const float EuNi = __expf(-u_i);

        const float SumEl  = sres[0];
        const float SumEu  = sres[1];
        const float SumEm  = sres[2];
        const float SumEmM = sres[3];

        const float S_l = EuNi * (SumEl - El_i);
        const float S_u = ElNi * (SumEu - Eu_i);
        float g_l = __fdividef(1.0f, 1.0f + S_l);
        float g_u = __fdividef(1.0f, 1.0f + S_u);
        float dg  = S_u - S_l;
        float m_l = -g_u * g_u;
        float m_u = __fdividef(g_u - g_l, dg + EPSf);
        if (fabsf(dg) < TINYf) m_u = m_l;
        const float c_u = g_l - m_u * S_l;
        const float c_l = g_u - m_l * S_u;

        const float m_i  = 0.5f * (l_i + u_i);
        const float Em_i = sqrt_apx(El_i * Eu_i);   // exp(m_i)
        const float EmNi = sqrt_apx(ElNi * EuNi);   // exp(-m_i)
        const float Al   = EmNi * (SumEm - Em_i);
        const float Bl   = (1.0f + m_i) * Al - EmNi * (SumEmM - Em_i * m_i);

        out[OFF_SL + row] = fminf(fmaxf(g_u, 0.0f), 1.0f);
        out[OFF_SU + row] = fminf(fmaxf(g_l, 0.0f), 1.0f);
        out[OFF_LB + row] = m_l * Bl + c_l;

        rowc[r][0] = ElNi;
        rowc[r][1] = EuNi;
        rowc[r][2] = (u_i - l_i) + EPSf;
        rowc[r][3] = m_u;
        rowc[r][4] = m_l * EmNi;        // fl: lower coef = fl * Em_j
        rowc[r][5] = m_l * (-Al);       // lower diag value
        rowc[r][6] = S_l;
        rowc[r][7] = c_u;
        rowc[r][8] = El_i * EuNi;       // el at diagonal (bitwise = loop's)
        rowc[r][9] = Eu_i * ElNi;       // eu at diagonal
    }
    __syncthreads();

    // main loop: 8 rows, stores fused, partials straight to smem
#pragma unroll
    for (int r = 0; r < ROWS_; ++r) {
        const float ElNr = rowc[r][0];
        const float EuNr = rowc[r][1];
        const float wiEr = rowc[r][2];
        const float mur  = rowc[r][3];
        const float flr  = rowc[r][4];
        float aAu = 0.f, aAuL = 0.f;
        float4 ocu, ocl;
        float* up = reinterpret_cast<float*>(&ocu);
        float* lp = reinterpret_cast<float*>(&ocl);
#pragma unroll
        for (int k = 0; k < 4; ++k) {
            float el  = Elj[k] * EuNr;           // exp(l_j - u_i)
            float eu  = Euj[k] * ElNr;           // exp(u_j - l_i)
            float a_u = __fdividef(eu - el, wj[k] + wiEr);
            aAu  += a_u;
            aAuL  = fmaf(a_u, ljp[k], aAuL);
            up[k] = mur * a_u;
            lp[k] = flr * Emj[k];
        }
        const size_t base = (size_t)(row0 + r) * C_ + j0;
        *reinterpret_cast<float4*>(out + OFF_UC + base) = ocu;
        *reinterpret_cast<float4*>(out + OFF_LC + base) = ocl;
        sred[2 * r    ][tid] = aAu;
        sred[2 * r + 1][tid] = aAuL;
    }
    __syncthreads();

    // transpose-reduce 16 partials: each warp reduces 2 variables
    {
        const int warp = tid >> 5;
        const int lane = tid & 31;
#pragma unroll
        for (int h = 0; h < 2; ++h) {
            const int v = warp + 8 * h;
            float s = 0.f;
#pragma unroll
            for (int jj = 0; jj < 8; ++jj) s += sred[v][lane + 32 * jj];
#pragma unroll
            for (int m = 16; m > 0; m >>= 1) s += __shfl_xor_sync(0xffffffffu, s, m);
            if (lane == 0) sres[v] = s;
        }
    }
    __syncthreads();

    // finalize: upper bias + diagonal coef entries (barrier orders overwrite)
    if (tid < ROWS_) {
        const int r   = tid;
        const int row = row0 + r;
        float Au  = sres[2 * r];
        float AuL = sres[2 * r + 1];

        const float l_i  = lrow[i0 + r];
        const float u_i  = urow[i0 + r];
        const float wiEr = rowc[r][2];
        const float m_u  = rowc[r][3];
        const float S_l  = rowc[r][6];
        const float c_u  = rowc[r][7];

        // subtract diagonal a_u exactly as the main loop computed it
        {
            float el_d = rowc[r][8];
            float eu_d = rowc[r][9];
            float a_ud = __fdividef(eu_d - el_d, (u_i - l_i) + wiEr);
            Au  -= a_ud;
            AuL -= a_ud * l_i;
        }
        const float Bu = S_l - AuL + u_i * Au;
        out[OFF_UB + row] = m_u * Bu + c_u;

        const size_t dbase = (size_t)row * C_ + (size_t)(i0 + r);
        out[OFF_UC + dbase] = m_u * (-Au);
        out[OFF_LC + dbase] = rowc[r][5];
    }
}

extern "C" void kernel_launch(void* const* d_in, const int* in_sizes, int n_in,
                              void* d_out, int out_size) {
    const float* lower = (const float*)d_in[0];
    const float* upper = (const float*)d_in[1];
    float* out = (float*)d_out;
    bs_kernel<<<BC_ / ROWS_, 256>>>(lower, upper, out);
}

// round 16
// speedup vs baseline: 1.1469x; 1.1469x over previous
#include <cuda_runtime.h>
#include <math.h>

#define B_   16
#define C_   1024
#define BC_  (B_ * C_)
#define EPSf  1e-12f
#define TINYf 1e-9f
#define ROWS_ 8

#define BCC_    ((size_t)BC_ * (size_t)C_)
#define OFF_SL  ((size_t)0)
#define OFF_SU  ((size_t)BC_)
#define OFF_LC  ((size_t)(2 * BC_))
#define OFF_UC  ((size_t)(2 * BC_) + BCC_)
#define OFF_LB  ((size_t)(2 * BC_) + 2 * BCC_)
#define OFF_UB  ((size_t)(2 * BC_) + 2 * BCC_ + BC_)

__device__ __forceinline__ float sqrt_apx(float x) {
    float r;
    asm("sqrt.approx.f32 %0, %1;" : "=f"(r) : "f"(x));
    return r;
}

// Single fused kernel: one block per 8 rows of one batch (R11 structure).
__global__ __launch_bounds__(256, 6) void bs_kernel(
    const float* __restrict__ lower,
    const float* __restrict__ upper,
    float* __restrict__ out)
{
    const int row0 = blockIdx.x << 3;        // b*C + i0
    const int b    = row0 >> 10;
    const int i0   = row0 & (C_ - 1);
    const int tid  = threadIdx.x;
    const int j0   = tid << 2;

    const float* __restrict__ lrow = lower + (size_t)b * C_;
    const float* __restrict__ urow = upper + (size_t)b * C_;

    // j-chunk loads
    float4 lj = *reinterpret_cast<const float4*>(lrow + j0);
    float4 uj = *reinterpret_cast<const float4*>(urow + j0);
    const float* ljp = reinterpret_cast<const float*>(&lj);
    const float* ujp = reinterpret_cast<const float*>(&uj);

    // per-j exponentials (computed, not loaded)
    float Elj[4], Euj[4], Emj[4], wj[4];
    float pEl = 0.f, pEu = 0.f, pEm = 0.f, pEmM = 0.f;
#pragma unroll
    for (int k = 0; k < 4; ++k) {
        float l = ljp[k], u = ujp[k];
        Elj[k] = __expf(l);
        Euj[k] = __expf(u);
        Emj[k] = sqrt_apx(Elj[k] * Euj[k]);   // exp((l+u)/2)
        wj[k]  = u - l;
        pEl  += Elj[k];
        pEu  += Euj[k];
        pEm  += Emj[k];
        pEmM  = fmaf(Emj[k], 0.5f * (l + u), pEmM);
    }

    __shared__ float  sred[16][256];
    __shared__ float  sres[16];
    __shared__ float4 rowk[ROWS_];      // {ElN, EuN, wiE, m_u} per row
    __shared__ float  rowf[ROWS_];      // flr per row
    __shared__ float  rowc[ROWS_][6];   // finalize scalars

    // block-reduce the 4 batch sums (warp w reduces var w)
    sred[0][tid] = pEl;
    sred[1][tid] = pEu;
    sred[2][tid] = pEm;
    sred[3][tid] = pEmM;
    __syncthreads();
    {
        const int warp = tid >> 5;
        const int lane = tid & 31;
        if (warp < 4) {
            float s = 0.f;
#pragma unroll
            for (int jj = 0; jj < 8; ++jj) s += sred[warp][lane + 32 * jj];
#pragma unroll
            for (int m = 16; m > 0; m >>= 1) s += __shfl_xor_sync(0xffffffffu, s, m);
            if (lane == 0) sres[warp] = s;
        }
    }
    __syncthreads();

    // per-row constants (8 threads)
    if (tid < ROWS_) {
        const int r   = tid;
        const int row = row0 + r;
        const float l_i  = lrow[i0 + r];
        const float u_i  = urow[i0 + r];
        const float El_i = __expf(l_i);
        const float Eu_i = __expf(u_i);
        const float ElNi = __expf(-l_i);
        const float EuNi = __expf(-u_i);

        const float SumEl  = sres[0];
        const float SumEu  = sres[1];
        const float SumEm  = sres[2];
        const float SumEmM = sres[3];

        const float S_l = EuNi * (SumEl - El_i);
        const float S_u = ElNi * (SumEu - Eu_i);
        float g_l = __fdividef(1.0f, 1.0f + S_l);
        float g_u = __fdividef(1.0f, 1.0f + S_u);
        float dg  = S_u - S_l;
        float m_l = -g_u * g_u;
        float m_u = __fdividef(g_u - g_l, dg + EPSf);
        if (fabsf(dg) < TINYf) m_u = m_l;
        const float c_u = g_l - m_u * S_l;
        const float c_l = g_u - m_l * S_u;

        const float m_i  = 0.5f * (l_i + u_i);
        const float Em_i = sqrt_apx(El_i * Eu_i);   // exp(m_i)
        const float EmNi = sqrt_apx(ElNi * EuNi);   // exp(-m_i)
        const float Al   = EmNi * (SumEm - Em_i);
        const float Bl   = (1.0f + m_i) * Al - EmNi * (SumEmM - Em_i * m_i);

        out[OFF_SL + row] = fminf(fmaxf(g_u, 0.0f), 1.0f);
        out[OFF_SU + row] = fminf(fmaxf(g_l, 0.0f), 1.0f);
        out[OFF_LB + row] = m_l * Bl + c_l;

        const float wiE = (u_i - l_i) + EPSf;
        rowk[r] = make_float4(ElNi, EuNi, wiE, m_u);
        rowf[r] = m_l * EmNi;           // fl: lower coef = fl * Em_j

        rowc[r][0] = wiE;
        rowc[r][1] = m_u;
        rowc[r][2] = S_l;
        rowc[r][3] = c_u;
        rowc[r][4] = m_l * (-Al);                       // lower diag value
        // diagonal num, same FFMA form as the loop: fmaf(Eu_i, ElNi, -el_d)
        rowc[r][5] = fmaf(Eu_i, ElNi, -(El_i * EuNi));
    }
    __syncthreads();

    // main loop: 8 rows, stores fused, partials straight to smem
#pragma unroll
    for (int r = 0; r < ROWS_; ++r) {
        const float4 rk  = rowk[r];     // one LDS.128
        const float  flr = rowf[r];     // one LDS.32
        const float ElNr = rk.x;
        const float EuNr = rk.y;
        const float wiEr = rk.z;
        const float mur  = rk.w;
        float aAu = 0.f, aAuL = 0.f;
        float4 ocu, ocl;
        float* up = reinterpret_cast<float*>(&ocu);
        float* lp = reinterpret_cast<float*>(&ocl);
#pragma unroll
        for (int k = 0; k < 4; ++k) {
            float el  = Elj[k] * EuNr;                 // exp(l_j - u_i)
            float num = fmaf(Euj[k], ElNr, -el);       // exp(u_j-l_i) - el
            float a_u = __fdividef(num, wj[k] + wiEr);
            aAu  += a_u;
            aAuL  = fmaf(a_u, ljp[k], aAuL);
            up[k] = mur * a_u;
            lp[k] = flr * Emj[k];
        }
        const size_t base = (size_t)(row0 + r) * C_ + j0;
        *reinterpret_cast<float4*>(out + OFF_UC + base) = ocu;
        *reinterpret_cast<float4*>(out + OFF_LC + base) = ocl;
        sred[2 * r    ][tid] = aAu;
        sred[2 * r + 1][tid] = aAuL;
    }
    __syncthreads();

    // transpose-reduce 16 partials: each warp reduces 2 variables
    {
        const int warp = tid >> 5;
        const int lane = tid & 31;
#pragma unroll
        for (int h = 0; h < 2; ++h) {
            const int v = warp + 8 * h;
            float s = 0.f;
#pragma unroll
            for (int jj = 0; jj < 8; ++jj) s += sred[v][lane + 32 * jj];
#pragma unroll
            for (int m = 16; m > 0; m >>= 1) s += __shfl_xor_sync(0xffffffffu, s, m);
            if (lane == 0) sres[v] = s;
        }
    }
    __syncthreads();

    // finalize: upper bias + diagonal coef entries (barrier orders overwrite)
    if (tid < ROWS_) {
        const int r   = tid;
        const int row = row0 + r;
        float Au  = sres[2 * r];
        float AuL = sres[2 * r + 1];

        const float l_i  = lrow[i0 + r];
        const float u_i  = urow[i0 + r];
        const float wiEr = rowc[r][0];
        const float m_u  = rowc[r][1];
        const float S_l  = rowc[r][2];
        const float c_u  = rowc[r][3];

        // subtract diagonal a_u exactly as the main loop computed it
        {
            float a_ud = __fdividef(rowc[r][5], (u_i - l_i) + wiEr);
            Au  -= a_ud;
            AuL -= a_ud * l_i;
        }
        const float Bu = S_l - AuL + u_i * Au;
        out[OFF_UB + row] = m_u * Bu + c_u;

        const size_t dbase = (size_t)row * C_ + (size_t)(i0 + r);
        out[OFF_UC + dbase] = m_u * (-Au);
        out[OFF_LC + dbase] = rowc[r][4];
    }
}

extern "C" void kernel_launch(void* const* d_in, const int* in_sizes, int n_in,
                              void* d_out, int out_size) {
    const float* lower = (const float*)d_in[0];
    const float* upper = (const float*)d_in[1];
    float* out = (float*)d_out;
    bs_kernel<<<BC_ / ROWS_, 256>>>(lower, upper, out);
}